// round 14
// baseline (speedup 1.0000x reference)
#include <cuda_runtime.h>
#include <cstdint>

#define N_TOTAL   4096
#define NN_NODES  1024
#define NN_MARB   3072
#define NN_EATERS 64
#define EPS_F     1e-6f
#define NWARPS    16
#define NBODY_BLOCKS 128

__device__ __forceinline__ float rsqrt_fast(float x) {
    float r;
    asm("rsqrt.approx.f32 %0, %1;" : "=f"(r) : "f"(x));
    return r;
}

// Eater-pair handshake state.
__device__ float2 g_epart[2][NN_EATERS];   // per-j-half eater force partials
__device__ float2 g_eater_pos[NN_EATERS];  // integrated eater pos_new
__device__ int    g_ectr = 0;              // eater-pair arrival ticket
__device__ int    g_eater_ready = 0;       // set by 2nd eater block
__device__ int    g_done = 0;              // marble blocks; 96th resets flag

// grid 130 x 512 threads.
//  blk 0..127 : normal n-body blocks (32 i-bodies each; warps split j 16-way
//               over 2 shared tiles of 2048). Marble blocks (32..127) then
//               wait ONLY on the eater pair and compute eaten inline.
//  blk 128/129: eater blocks — compute forces on the 64 eater nodes against
//               j-half (blk-128). Second to arrive integrates and publishes
//               g_eater_pos. These blocks finish EARLY (half a block's work),
//               so marble blocks wait on max-of-2-early, not max-of-32.
__global__ __launch_bounds__(512, 1)
void nbody_fused_kernel(const float* __restrict__ pos,
                        const float* __restrict__ vel,
                        const float* __restrict__ mass,
                        const int*   __restrict__ eidx,
                        const float* __restrict__ erad,
                        const float* __restrict__ dtp,
                        float* __restrict__ out) {
    __shared__ float4 sh[2048];                 // (x, y, m, 0)   32 KB
    __shared__ float2 spart[NWARPS][64];        // reductions (both paths) 8 KB
    __shared__ float  s_ex[NN_EATERS], s_ey[NN_EATERS], s_er2[NN_EATERS];
    __shared__ int    s_tk;

    const int tid  = threadIdx.x;
    const int lane = tid & 31;
    const int warp = tid >> 5;
    const int blk  = blockIdx.x;

    // ======================= EATER BLOCKS =======================
    if (blk >= NBODY_BLOCKS) {
        const int jh = blk - NBODY_BLOCKS;      // j-half 0/1

        // Fill this half's 2048-body tile (4 bodies/thread).
        #pragma unroll
        for (int k = 0; k < 4; k++) {
            const int j  = k * 512 + tid;
            const int gj = jh * 2048 + j;
            float2 q = ((const float2*)pos)[gj];
            sh[j] = make_float4(q.x, q.y, mass[gj], 0.0f);
        }

        // Two eaters per lane.
        const int   e0  = eidx[lane];
        const int   e1  = eidx[lane + 32];
        const float2 pe0 = ((const float2*)pos)[e0];
        const float2 pe1 = ((const float2*)pos)[e1];
        __syncthreads();

        float ax0 = 0.0f, ay0 = 0.0f, ax1 = 0.0f, ay1 = 0.0f;
        const int base = warp * 128;            // 128 j per warp
        #pragma unroll 4
        for (int jj = 0; jj < 128; jj++) {
            const float4 q = sh[base + jj];
            {
                const float dx = q.x - pe0.x;
                const float dy = q.y - pe0.y;
                const float d2 = fmaf(dx, dx, fmaf(dy, dy, EPS_F));
                const float r  = rsqrt_fast(d2);
                const float w  = r * r * r * q.z;
                ax0 = fmaf(w, dx, ax0);
                ay0 = fmaf(w, dy, ay0);
            }
            {
                const float dx = q.x - pe1.x;
                const float dy = q.y - pe1.y;
                const float d2 = fmaf(dx, dx, fmaf(dy, dy, EPS_F));
                const float r  = rsqrt_fast(d2);
                const float w  = r * r * r * q.z;
                ax1 = fmaf(w, dx, ax1);
                ay1 = fmaf(w, dy, ay1);
            }
        }
        spart[warp][lane]      = make_float2(ax0, ay0);
        spart[warp][lane + 32] = make_float2(ax1, ay1);
        __syncthreads();

        float fx = 0.0f, fy = 0.0f;
        if (tid < NN_EATERS) {
            #pragma unroll
            for (int w = 0; w < NWARPS; w++) {
                fx += spart[w][tid].x;
                fy += spart[w][tid].y;
            }
            g_epart[jh][tid] = make_float2(fx, fy);
        }
        __syncthreads();
        if (tid == 0) {
            __threadfence();                    // publish partials
            s_tk = atomicAdd(&g_ectr, 1);
        }
        __syncthreads();
        if (s_tk == 0) return;                  // first eater block: done

        // Second eater block: combine halves, integrate, publish.
        if (tid == 0) {
            g_ectr = 0;                         // reset for next replay
            __threadfence();                    // acquire other half
        }
        __syncthreads();
        if (tid < NN_EATERS) {
            const float2 oth = __ldcg(&g_epart[jh ^ 1][tid]);
            const int    e   = eidx[tid];
            const float2 pe  = ((const float2*)pos)[e];
            const float2 ve  = ((const float2*)vel)[e];
            const float  dt  = dtp[0];
            const float  vx  = ve.x + (fx + oth.x) * dt;
            const float  vy  = ve.y + (fy + oth.y) * dt;
            g_eater_pos[tid] = make_float2(pe.x + vx * dt, pe.y + vy * dt);
        }
        __syncthreads();
        if (tid == 0) {
            __threadfence();                    // publish eater positions
            atomicExch(&g_eater_ready, 1);
        }
        return;
    }

    // ======================= NORMAL BLOCKS =======================
    const int  i = blk * 32 + lane;
    const bool is_marble_blk = (blk >= 32);

    if (is_marble_blk && tid < NN_EATERS) {
        const float r = erad[tid];
        s_er2[tid] = r * r;
    }

    const float2 p = ((const float2*)pos)[i];
    const float px = p.x, py = p.y;

    float ax = 0.0f, ay = 0.0f;

    #pragma unroll
    for (int tile = 0; tile < 2; tile++) {
        #pragma unroll
        for (int k = 0; k < 4; k++) {
            const int j  = k * 512 + tid;
            const int gj = tile * 2048 + j;
            float2 q = ((const float2*)pos)[gj];
            sh[j] = make_float4(q.x, q.y, mass[gj], 0.0f);
        }
        __syncthreads();

        const int base = warp * 128;            // 128 bodies per warp
        #pragma unroll 8
        for (int jj = 0; jj < 128; jj++) {
            const float4 q = sh[base + jj];     // LDS.128, warp-uniform
            const float dx = q.x - px;
            const float dy = q.y - py;
            const float d2 = fmaf(dx, dx, fmaf(dy, dy, EPS_F));
            const float r  = rsqrt_fast(d2);    // MUFU.RSQ
            const float r2 = r * r;
            const float mr = r * q.z;
            const float w  = r2 * mr;           // m_j * (d2+eps)^-1.5
            // Coincident pair (incl. j==i): dx=dy=0 -> contributes 0,
            // matching the reference's masked inv_d3.
            ax = fmaf(w, dx, ax);
            ay = fmaf(w, dy, ay);
        }
        __syncthreads();
    }

    spart[warp][lane] = make_float2(ax, ay);
    __syncthreads();

    float nx = 0.0f, ny = 0.0f;
    if (warp == 0) {
        float fx = 0.0f, fy = 0.0f;
        #pragma unroll
        for (int w = 0; w < NWARPS; w++) {
            fx += spart[w][lane].x;
            fy += spart[w][lane].y;
        }
        const float dt = dtp[0];
        const float vx = vel[2 * i]     + fx * dt;
        const float vy = vel[2 * i + 1] + fy * dt;
        nx = px + vx * dt;
        ny = py + vy * dt;
        // state_new = stack([pos_new, vel_new]) : pos block first, then vel.
        out[2 * i]                   = nx;
        out[2 * i + 1]               = ny;
        out[2 * N_TOTAL + 2 * i]     = vx;
        out[2 * N_TOTAL + 2 * i + 1] = vy;
    }

    if (!is_marble_blk) return;                 // node blocks: done

    // ---- Marble block: wait ONLY on the (early-finishing) eater pair ----
    if (tid == 0) {
        while (*((volatile int*)&g_eater_ready) == 0) {
            __nanosleep(64);
        }
        __threadfence();                        // acquire g_eater_pos
    }
    __syncthreads();

    if (tid < NN_EATERS) {
        const float2 ep = __ldcg(&g_eater_pos[tid]);
        s_ex[tid] = ep.x;
        s_ey[tid] = ep.y;
    }
    __syncthreads();

    if (warp == 0) {
        int eaten = 0;
        #pragma unroll
        for (int k = 0; k < NN_EATERS; k++) {
            const float dx = nx - s_ex[k];
            const float dy = ny - s_ey[k];
            const float d2 = fmaf(dx, dx, dy * dy);
            eaten |= (d2 <= s_er2[k]);
        }
        const int m = i - NN_NODES;             // marble index 0..3071
        out[4 * N_TOTAL + m] = eaten ? 1.0f : 0.0f;
    }
    __syncthreads();

    // Last marble block resets the flag for the next graph replay.
    if (tid == 0) {
        const int d = atomicAdd(&g_done, 1);
        if (d == 95) {
            g_done = 0;
            atomicExch(&g_eater_ready, 0);
        }
    }
}

extern "C" void kernel_launch(void* const* d_in, const int* in_sizes, int n_in,
                              void* d_out, int out_size) {
    const float* positions  = (const float*)d_in[0];
    const float* velocities = (const float*)d_in[1];
    const float* masses     = (const float*)d_in[2];
    const int*   eater_idx  = (const int*)  d_in[3];
    const float* eater_rad  = (const float*)d_in[4];
    const float* dt         = (const float*)d_in[5];
    float* out = (float*)d_out;

    nbody_fused_kernel<<<NBODY_BLOCKS + 2, 512>>>(positions, velocities, masses,
                                                  eater_idx, eater_rad, dt, out);
}

// round 15
// speedup vs baseline: 1.1366x; 1.1366x over previous
#include <cuda_runtime.h>
#include <cstdint>

#define N_TOTAL   4096
#define NN_NODES  1024
#define NN_MARB   3072
#define NN_EATERS 64
#define EPS_F     1e-6f
#define NWARPS    16
#define NBODY_BLOCKS 128
#define NE_BLOCKS 4                       // eater blocks, quarter j-slices

__device__ __forceinline__ float rsqrt_fast(float x) {
    float r;
    asm("rsqrt.approx.f32 %0, %1;" : "=f"(r) : "f"(x));
    return r;
}

// Eater handshake state.
__device__ float2 g_epart[NE_BLOCKS][NN_EATERS]; // per-quarter force partials
__device__ float2 g_eater_pos[NN_EATERS];        // integrated eater pos_new
__device__ int    g_ectr = 0;                    // eater arrival ticket
__device__ int    g_eater_ready = 0;             // set by 4th eater block
__device__ int    g_done = 0;                    // marble blocks; 96th resets

// grid 132 x 512 threads.
//  blk 0..127  : normal n-body blocks (32 i each; warps split j 16-way over
//                2 tiles of 2048). Marble blocks (32..127) then wait ONLY on
//                the early-finishing eater quartet and compute eaten inline.
//  blk 128..131: eater blocks — force on the 64 eater nodes vs a QUARTER
//                j-slice (1024 j) => 128 pairs/warp = HALF a normal block's
//                work => they finish early. 4th arrival combines quarters,
//                integrates, publishes g_eater_pos well before marbles need it.
__global__ __launch_bounds__(512, 1)
void nbody_fused_kernel(const float* __restrict__ pos,
                        const float* __restrict__ vel,
                        const float* __restrict__ mass,
                        const int*   __restrict__ eidx,
                        const float* __restrict__ erad,
                        const float* __restrict__ dtp,
                        float* __restrict__ out) {
    __shared__ float4 sh[2048];                 // (x, y, m, 0)   32 KB
    __shared__ float2 spart[NWARPS][64];        // reductions     8 KB
    __shared__ float  s_ex[NN_EATERS], s_ey[NN_EATERS], s_er2[NN_EATERS];
    __shared__ int    s_tk;

    const int tid  = threadIdx.x;
    const int lane = tid & 31;
    const int warp = tid >> 5;
    const int blk  = blockIdx.x;

    // ======================= EATER BLOCKS =======================
    if (blk >= NBODY_BLOCKS) {
        const int jq = blk - NBODY_BLOCKS;      // j-quarter 0..3

        // Fill this quarter's 1024-body tile (2 bodies/thread).
        #pragma unroll
        for (int k = 0; k < 2; k++) {
            const int j  = k * 512 + tid;
            const int gj = jq * 1024 + j;
            float2 q = ((const float2*)pos)[gj];
            sh[j] = make_float4(q.x, q.y, mass[gj], 0.0f);
        }

        // Two eaters per lane.
        const int    e0  = eidx[lane];
        const int    e1  = eidx[lane + 32];
        const float2 pe0 = ((const float2*)pos)[e0];
        const float2 pe1 = ((const float2*)pos)[e1];
        __syncthreads();

        float ax0 = 0.0f, ay0 = 0.0f, ax1 = 0.0f, ay1 = 0.0f;
        const int base = warp * 64;             // 64 j per warp (quarter/16)
        #pragma unroll 4
        for (int jj = 0; jj < 64; jj++) {
            const float4 q = sh[base + jj];
            {
                const float dx = q.x - pe0.x;
                const float dy = q.y - pe0.y;
                const float d2 = fmaf(dx, dx, fmaf(dy, dy, EPS_F));
                const float r  = rsqrt_fast(d2);
                const float w  = r * r * r * q.z;
                ax0 = fmaf(w, dx, ax0);
                ay0 = fmaf(w, dy, ay0);
            }
            {
                const float dx = q.x - pe1.x;
                const float dy = q.y - pe1.y;
                const float d2 = fmaf(dx, dx, fmaf(dy, dy, EPS_F));
                const float r  = rsqrt_fast(d2);
                const float w  = r * r * r * q.z;
                ax1 = fmaf(w, dx, ax1);
                ay1 = fmaf(w, dy, ay1);
            }
        }
        spart[warp][lane]      = make_float2(ax0, ay0);
        spart[warp][lane + 32] = make_float2(ax1, ay1);
        __syncthreads();

        if (tid < NN_EATERS) {
            float fx = 0.0f, fy = 0.0f;
            #pragma unroll
            for (int w = 0; w < NWARPS; w++) {
                fx += spart[w][tid].x;
                fy += spart[w][tid].y;
            }
            g_epart[jq][tid] = make_float2(fx, fy);
        }
        __syncthreads();
        if (tid == 0) {
            __threadfence();                    // publish partials
            s_tk = atomicAdd(&g_ectr, 1);
        }
        __syncthreads();
        if (s_tk != NE_BLOCKS - 1) return;      // not last: done

        // Last eater block: combine all quarters, integrate, publish.
        if (tid == 0) {
            g_ectr = 0;                         // reset for next replay
            __threadfence();                    // acquire other quarters
        }
        __syncthreads();
        if (tid < NN_EATERS) {
            float fx = 0.0f, fy = 0.0f;
            #pragma unroll
            for (int qq = 0; qq < NE_BLOCKS; qq++) {
                const float2 pp = __ldcg(&g_epart[qq][tid]);
                fx += pp.x;
                fy += pp.y;
            }
            const int    e  = eidx[tid];
            const float2 pe = ((const float2*)pos)[e];
            const float2 ve = ((const float2*)vel)[e];
            const float  dt = dtp[0];
            const float  vx = ve.x + fx * dt;
            const float  vy = ve.y + fy * dt;
            g_eater_pos[tid] = make_float2(pe.x + vx * dt, pe.y + vy * dt);
        }
        __syncthreads();
        if (tid == 0) {
            __threadfence();                    // publish eater positions
            atomicExch(&g_eater_ready, 1);
        }
        return;
    }

    // ======================= NORMAL BLOCKS =======================
    const int  i = blk * 32 + lane;
    const bool is_marble_blk = (blk >= 32);

    if (is_marble_blk && tid < NN_EATERS) {
        const float r = erad[tid];
        s_er2[tid] = r * r;
    }

    const float2 p = ((const float2*)pos)[i];
    const float px = p.x, py = p.y;

    float ax = 0.0f, ay = 0.0f;

    #pragma unroll
    for (int tile = 0; tile < 2; tile++) {
        #pragma unroll
        for (int k = 0; k < 4; k++) {
            const int j  = k * 512 + tid;
            const int gj = tile * 2048 + j;
            float2 q = ((const float2*)pos)[gj];
            sh[j] = make_float4(q.x, q.y, mass[gj], 0.0f);
        }
        __syncthreads();

        const int base = warp * 128;            // 128 bodies per warp
        #pragma unroll 8
        for (int jj = 0; jj < 128; jj++) {
            const float4 q = sh[base + jj];     // LDS.128, warp-uniform
            const float dx = q.x - px;
            const float dy = q.y - py;
            const float d2 = fmaf(dx, dx, fmaf(dy, dy, EPS_F));
            const float r  = rsqrt_fast(d2);    // MUFU.RSQ
            const float r2 = r * r;
            const float mr = r * q.z;
            const float w  = r2 * mr;           // m_j * (d2+eps)^-1.5
            // Coincident pair (incl. j==i): dx=dy=0 -> contributes 0,
            // matching the reference's masked inv_d3.
            ax = fmaf(w, dx, ax);
            ay = fmaf(w, dy, ay);
        }
        __syncthreads();
    }

    spart[warp][lane] = make_float2(ax, ay);
    __syncthreads();

    float nx = 0.0f, ny = 0.0f;
    if (warp == 0) {
        float fx = 0.0f, fy = 0.0f;
        #pragma unroll
        for (int w = 0; w < NWARPS; w++) {
            fx += spart[w][lane].x;
            fy += spart[w][lane].y;
        }
        const float dt = dtp[0];
        const float vx = vel[2 * i]     + fx * dt;
        const float vy = vel[2 * i + 1] + fy * dt;
        nx = px + vx * dt;
        ny = py + vy * dt;
        // state_new = stack([pos_new, vel_new]) : pos block first, then vel.
        out[2 * i]                   = nx;
        out[2 * i + 1]               = ny;
        out[2 * N_TOTAL + 2 * i]     = vx;
        out[2 * N_TOTAL + 2 * i + 1] = vy;
    }

    if (!is_marble_blk) return;                 // node blocks: done

    // ---- Marble block: wait on the EARLY-finishing eater quartet ----
    if (tid == 0) {
        while (*((volatile int*)&g_eater_ready) == 0) {
            __nanosleep(64);
        }
        __threadfence();                        // acquire g_eater_pos
    }
    __syncthreads();

    if (tid < NN_EATERS) {
        const float2 ep = __ldcg(&g_eater_pos[tid]);
        s_ex[tid] = ep.x;
        s_ey[tid] = ep.y;
    }
    __syncthreads();

    if (warp == 0) {
        int eaten = 0;
        #pragma unroll
        for (int k = 0; k < NN_EATERS; k++) {
            const float dx = nx - s_ex[k];
            const float dy = ny - s_ey[k];
            const float d2 = fmaf(dx, dx, dy * dy);
            eaten |= (d2 <= s_er2[k]);
        }
        const int m = i - NN_NODES;             // marble index 0..3071
        out[4 * N_TOTAL + m] = eaten ? 1.0f : 0.0f;
    }
    __syncthreads();

    // Last marble block resets the flag for the next graph replay.
    if (tid == 0) {
        const int d = atomicAdd(&g_done, 1);
        if (d == 95) {
            g_done = 0;
            atomicExch(&g_eater_ready, 0);
        }
    }
}

extern "C" void kernel_launch(void* const* d_in, const int* in_sizes, int n_in,
                              void* d_out, int out_size) {
    const float* positions  = (const float*)d_in[0];
    const float* velocities = (const float*)d_in[1];
    const float* masses     = (const float*)d_in[2];
    const int*   eater_idx  = (const int*)  d_in[3];
    const float* eater_rad  = (const float*)d_in[4];
    const float* dt         = (const float*)d_in[5];
    float* out = (float*)d_out;

    nbody_fused_kernel<<<NBODY_BLOCKS + NE_BLOCKS, 512>>>(
        positions, velocities, masses, eater_idx, eater_rad, dt, out);
}

// round 16
// speedup vs baseline: 1.2827x; 1.1285x over previous
#include <cuda_runtime.h>
#include <cstdint>

#define N_TOTAL   4096
#define NN_NODES  1024
#define NN_MARB   3072
#define NN_EATERS 64
#define EPS_F     1e-6f
#define NWARPS    16
#define NBODY_BLOCKS 128
#define NE_BLOCKS 4                       // eater blocks, quarter j-slices
#define SMEM_DYN  (N_TOTAL * sizeof(float4))   // 64 KB j-tile

__device__ __forceinline__ float rsqrt_fast(float x) {
    float r;
    asm("rsqrt.approx.f32 %0, %1;" : "=f"(r) : "f"(x));
    return r;
}

// Eater handshake state.
__device__ float2 g_epart[NE_BLOCKS][NN_EATERS]; // per-quarter force partials
__device__ float2 g_eater_pos[NN_EATERS];        // integrated eater pos_new
__device__ int    g_ectr = 0;                    // eater arrival ticket
__device__ int    g_eater_ready = 0;             // set by 4th eater block
__device__ int    g_done = 0;                    // marble blocks; 96th resets

// grid 132 x 512 threads.
//  blk 0..127  : n-body blocks. ONE 64KB shared tile of all 4096 bodies,
//                one fill + one barrier, then each warp runs an
//                uninterrupted 256-j loop for its slice.
//  blk 128..131: eater blocks — 64 eater nodes vs a quarter j-slice
//                (half a normal block's pair count => finish early).
//                4th arrival integrates and publishes g_eater_pos.
//  Marble blocks: warp 1 overlaps the eater-pos gather with warp 0's
//                reduction, then warp 0 computes eaten inline.
__global__ __launch_bounds__(512, 1)
void nbody_fused_kernel(const float* __restrict__ pos,
                        const float* __restrict__ vel,
                        const float* __restrict__ mass,
                        const int*   __restrict__ eidx,
                        const float* __restrict__ erad,
                        const float* __restrict__ dtp,
                        float* __restrict__ out) {
    extern __shared__ float4 sh[];              // 4096 (x, y, m, 0)  64 KB
    __shared__ float2 spart[NWARPS][64];        // reductions          8 KB
    __shared__ float  s_ex[NN_EATERS], s_ey[NN_EATERS], s_er2[NN_EATERS];
    __shared__ int    s_tk;

    const int tid  = threadIdx.x;
    const int lane = tid & 31;
    const int warp = tid >> 5;
    const int blk  = blockIdx.x;

    // ======================= EATER BLOCKS =======================
    if (blk >= NBODY_BLOCKS) {
        const int jq = blk - NBODY_BLOCKS;      // j-quarter 0..3

        // Fill this quarter's 1024-body tile (2 bodies/thread).
        #pragma unroll
        for (int k = 0; k < 2; k++) {
            const int j  = k * 512 + tid;
            const int gj = jq * 1024 + j;
            float2 q = ((const float2*)pos)[gj];
            sh[j] = make_float4(q.x, q.y, mass[gj], 0.0f);
        }

        const int    e0  = eidx[lane];
        const int    e1  = eidx[lane + 32];
        const float2 pe0 = ((const float2*)pos)[e0];
        const float2 pe1 = ((const float2*)pos)[e1];
        __syncthreads();

        float ax0 = 0.0f, ay0 = 0.0f, ax1 = 0.0f, ay1 = 0.0f;
        const int base = warp * 64;             // 64 j per warp
        #pragma unroll 4
        for (int jj = 0; jj < 64; jj++) {
            const float4 q = sh[base + jj];
            {
                const float dx = q.x - pe0.x;
                const float dy = q.y - pe0.y;
                const float d2 = fmaf(dx, dx, fmaf(dy, dy, EPS_F));
                const float r  = rsqrt_fast(d2);
                const float w  = r * r * r * q.z;
                ax0 = fmaf(w, dx, ax0);
                ay0 = fmaf(w, dy, ay0);
            }
            {
                const float dx = q.x - pe1.x;
                const float dy = q.y - pe1.y;
                const float d2 = fmaf(dx, dx, fmaf(dy, dy, EPS_F));
                const float r  = rsqrt_fast(d2);
                const float w  = r * r * r * q.z;
                ax1 = fmaf(w, dx, ax1);
                ay1 = fmaf(w, dy, ay1);
            }
        }
        spart[warp][lane]      = make_float2(ax0, ay0);
        spart[warp][lane + 32] = make_float2(ax1, ay1);
        __syncthreads();

        if (tid < NN_EATERS) {
            float fx = 0.0f, fy = 0.0f;
            #pragma unroll
            for (int w = 0; w < NWARPS; w++) {
                fx += spart[w][tid].x;
                fy += spart[w][tid].y;
            }
            g_epart[jq][tid] = make_float2(fx, fy);
        }
        __syncthreads();
        if (tid == 0) {
            __threadfence();                    // publish partials
            s_tk = atomicAdd(&g_ectr, 1);
        }
        __syncthreads();
        if (s_tk != NE_BLOCKS - 1) return;      // not last: done

        if (tid == 0) {
            g_ectr = 0;                         // reset for next replay
            __threadfence();                    // acquire other quarters
        }
        __syncthreads();
        if (tid < NN_EATERS) {
            float fx = 0.0f, fy = 0.0f;
            #pragma unroll
            for (int qq = 0; qq < NE_BLOCKS; qq++) {
                const float2 pp = __ldcg(&g_epart[qq][tid]);
                fx += pp.x;
                fy += pp.y;
            }
            const int    e  = eidx[tid];
            const float2 pe = ((const float2*)pos)[e];
            const float2 ve = ((const float2*)vel)[e];
            const float  dt = dtp[0];
            const float  vx = ve.x + fx * dt;
            const float  vy = ve.y + fy * dt;
            g_eater_pos[tid] = make_float2(pe.x + vx * dt, pe.y + vy * dt);
        }
        __syncthreads();
        if (tid == 0) {
            __threadfence();                    // publish eater positions
            atomicExch(&g_eater_ready, 1);
        }
        return;
    }

    // ======================= NORMAL BLOCKS =======================
    const int  i = blk * 32 + lane;
    const bool is_marble_blk = (blk >= 32);

    if (is_marble_blk && tid < NN_EATERS) {
        const float r = erad[tid];
        s_er2[tid] = r * r;
    }

    const float2 p = ((const float2*)pos)[i];
    const float px = p.x, py = p.y;

    // Single fill: all 4096 bodies, 8 per thread, straight from global.
    #pragma unroll
    for (int k = 0; k < 8; k++) {
        const int j = k * 512 + tid;
        float2 q = ((const float2*)pos)[j];
        sh[j] = make_float4(q.x, q.y, mass[j], 0.0f);
    }
    __syncthreads();

    float ax = 0.0f, ay = 0.0f;
    const int base = warp * 256;                // 256 bodies per warp
    #pragma unroll 8
    for (int jj = 0; jj < 256; jj++) {
        const float4 q = sh[base + jj];         // LDS.128, warp-uniform
        const float dx = q.x - px;
        const float dy = q.y - py;
        const float d2 = fmaf(dx, dx, fmaf(dy, dy, EPS_F));
        const float r  = rsqrt_fast(d2);        // MUFU.RSQ
        const float r2 = r * r;
        const float mr = r * q.z;
        const float w  = r2 * mr;               // m_j * (d2+eps)^-1.5
        // Coincident pair (incl. j==i): dx=dy=0 -> contributes 0,
        // matching the reference's masked inv_d3.
        ax = fmaf(w, dx, ax);
        ay = fmaf(w, dy, ay);
    }

    spart[warp][lane] = make_float2(ax, ay);
    __syncthreads();

    // Warp 1 (marble blocks): gather eater positions while warp 0 reduces.
    if (is_marble_blk && warp == 1) {
        while (*((volatile int*)&g_eater_ready) == 0) {
            __nanosleep(64);
        }
        __threadfence();                        // acquire g_eater_pos
        {
            const float2 ep0 = __ldcg(&g_eater_pos[lane]);
            const float2 ep1 = __ldcg(&g_eater_pos[lane + 32]);
            s_ex[lane]      = ep0.x;  s_ey[lane]      = ep0.y;
            s_ex[lane + 32] = ep1.x;  s_ey[lane + 32] = ep1.y;
        }
    }

    float nx = 0.0f, ny = 0.0f;
    if (warp == 0) {
        float fx = 0.0f, fy = 0.0f;
        #pragma unroll
        for (int w = 0; w < NWARPS; w++) {
            fx += spart[w][lane].x;
            fy += spart[w][lane].y;
        }
        const float dt = dtp[0];
        const float vx = vel[2 * i]     + fx * dt;
        const float vy = vel[2 * i + 1] + fy * dt;
        nx = px + vx * dt;
        ny = py + vy * dt;
        // state_new = stack([pos_new, vel_new]) : pos block first, then vel.
        out[2 * i]                   = nx;
        out[2 * i + 1]               = ny;
        out[2 * N_TOTAL + 2 * i]     = vx;
        out[2 * N_TOTAL + 2 * i + 1] = vy;
    }

    if (!is_marble_blk) return;                 // node blocks: done

    __syncthreads();                            // s_ex/s_ey ready

    if (warp == 0) {
        int eaten = 0;
        #pragma unroll
        for (int k = 0; k < NN_EATERS; k++) {
            const float dx = nx - s_ex[k];
            const float dy = ny - s_ey[k];
            const float d2 = fmaf(dx, dx, dy * dy);
            eaten |= (d2 <= s_er2[k]);
        }
        const int m = i - NN_NODES;             // marble index 0..3071
        out[4 * N_TOTAL + m] = eaten ? 1.0f : 0.0f;
    }
    __syncthreads();

    // Last marble block resets the flag for the next graph replay.
    if (tid == 0) {
        const int d = atomicAdd(&g_done, 1);
        if (d == 95) {
            g_done = 0;
            atomicExch(&g_eater_ready, 0);
        }
    }
}

extern "C" void kernel_launch(void* const* d_in, const int* in_sizes, int n_in,
                              void* d_out, int out_size) {
    const float* positions  = (const float*)d_in[0];
    const float* velocities = (const float*)d_in[1];
    const float* masses     = (const float*)d_in[2];
    const int*   eater_idx  = (const int*)  d_in[3];
    const float* eater_rad  = (const float*)d_in[4];
    const float* dt         = (const float*)d_in[5];
    float* out = (float*)d_out;

    cudaFuncSetAttribute(nbody_fused_kernel,
                         cudaFuncAttributeMaxDynamicSharedMemorySize, SMEM_DYN);
    nbody_fused_kernel<<<NBODY_BLOCKS + NE_BLOCKS, 512, SMEM_DYN>>>(
        positions, velocities, masses, eater_idx, eater_rad, dt, out);
}